// round 6
// baseline (speedup 1.0000x reference)
#include <cuda_runtime.h>
#include <math.h>
#include <stdint.h>

// Problem constants
#define B_  32
#define S_  1024
#define D_  256
#define N_  32
#define C_  64

// pass kernel tiling
#define SCH 64                // s-values per block
#define CHUNKS (S_/SCH)       // 16
#define TPB 512               // threads per pass block
#define XPAD 260              // xS row stride (floats)
#define PPAD2 72              // pT2 row stride (words) per d-pair row
#define CPAD 36               // agree row stride
#define CS2PAD 68             // duplicated-coef row stride
#define WPAD 65               // W smem row stride (capsule)

// smem layout (floats): xS [SCH][XPAD] | pT2 [D_/2][PPAD2] (aliased by cS2 [SCH][CS2PAD]) | cS [SCH][CPAD]
#define OFF_PT2 (SCH*XPAD)
#define OFF_CS  (OFF_PT2 + (D_/2)*PPAD2)
#define PASS_SMEM ((OFF_CS + SCH*CPAD) * 4)                       // 112640 B
#define CAPS_SMEM ((D_*WPAD + 8*D_ + 8*C_ + 8*C_) * 4)            // 78848 B

// ---------------- scratch (device globals; no runtime allocation) ----------
__device__ float g_y0[B_*D_];          // (1/N) * sum_s x
__device__ float g_ya[B_*N_*D_];       // y for iter1
__device__ float g_yb[B_*N_*D_];       // y for iter2
__device__ float g_v [B_*N_*C_];
__device__ float g_p [B_*N_*D_];       // p[b,n,d] = sum_c W[n,d,c] v[b,n,c]
__device__ float g_logits[B_*S_*N_];

// packed f32x2 FMA: d += a * b (elementwise on 2 packed floats)
__device__ __forceinline__ void fma2(unsigned long long& d,
                                     unsigned long long a, unsigned long long b) {
    asm("fma.rn.f32x2 %0, %1, %2, %0;" : "+l"(d) : "l"(a), "l"(b));
}
__device__ __forceinline__ float2 unpack2(unsigned long long v) {
    float2 f;
    asm("mov.b64 {%0, %1}, %2;" : "=f"(f.x), "=f"(f.y) : "l"(v));
    return f;
}

// ---------------- zero ------------------------------------------------------
__global__ void zero_kernel() {
    int i = blockIdx.x * blockDim.x + threadIdx.x;
    if (i < B_*D_) g_y0[i] = 0.f;
    if (i < B_*N_*D_) { g_ya[i] = 0.f; g_yb[i] = 0.f; }
}

// ---------------- y0 = (1/N) * sum_s x --------------------------------------
__global__ __launch_bounds__(256) void reduce_x_kernel(const float* __restrict__ x) {
    const int b  = blockIdx.x >> 3;     // 32
    const int sg = blockIdx.x & 7;      // 8 groups x 128 s
    const int d  = threadIdx.x;
    const float* xp = x + ((size_t)b * S_ + sg * 128) * D_ + d;
    float a0 = 0.f, a1 = 0.f, a2 = 0.f, a3 = 0.f;
    #pragma unroll 8
    for (int s = 0; s < 128; s += 4) {
        a0 += xp[(s+0)*D_]; a1 += xp[(s+1)*D_];
        a2 += xp[(s+2)*D_]; a3 += xp[(s+3)*D_];
    }
    atomicAdd(&g_y0[b*D_ + d], (a0+a1+a2+a3) * (1.0f / (float)N_));
}

// ---------------- capsule: s = y@W, v = squash(s), p = W@v -------------------
__global__ __launch_bounds__(256) void capsule_kernel(const float* __restrict__ W,
                                                      int ysel, float* __restrict__ vout_ext,
                                                      int compute_p) {
    extern __shared__ float sm[];
    float* sW = sm;                 // [D_][WPAD]
    float* sy = sW + D_*WPAD;       // [8][D_]
    float* ss = sy + 8*D_;          // [8][C_]
    float* sv = ss + 8*C_;          // [8][C_]

    const int n  = blockIdx.x;
    const int b0 = blockIdx.y * 8;
    const int t  = threadIdx.x;

    const float* Wn = W + (size_t)n * D_ * C_;
    for (int i = t; i < D_*C_; i += 256) {
        int d = i >> 6, c = i & 63;
        sW[d*WPAD + c] = Wn[i];
    }
    const float* ysrc = (ysel == 0) ? g_y0 : (ysel == 1) ? g_ya : g_yb;
    for (int i = t; i < 8*D_; i += 256) {
        int bb = i >> 8, d = i & 255;
        sy[bb*D_ + d] = (ysel == 0) ? ysrc[(b0+bb)*D_ + d]
                                    : ysrc[((size_t)(b0+bb)*N_ + n)*D_ + d];
    }
    __syncthreads();

    {
        const int c = t & 63, bt = t >> 6;
        float s0 = 0.f, s1 = 0.f;
        const float* y0r = sy + (bt*2+0)*D_;
        const float* y1r = sy + (bt*2+1)*D_;
        #pragma unroll 4
        for (int d = 0; d < D_; d++) {
            float w = sW[d*WPAD + c];
            s0 += y0r[d] * w;
            s1 += y1r[d] * w;
        }
        ss[(bt*2+0)*C_ + c] = s0;
        ss[(bt*2+1)*C_ + c] = s1;
    }
    __syncthreads();

    const int wid = t >> 5, lane = t & 31;
    {
        float a0 = ss[wid*C_ + lane];
        float a1 = ss[wid*C_ + 32 + lane];
        float sq = a0*a0 + a1*a1;
        #pragma unroll
        for (int o = 16; o > 0; o >>= 1) sq += __shfl_xor_sync(0xffffffffu, sq, o);
        float sc = (sq / (1.f + sq)) * rsqrtf(sq + 1e-8f);
        float v0 = a0 * sc, v1 = a1 * sc;
        sv[wid*C_ + lane]      = v0;
        sv[wid*C_ + 32 + lane] = v1;
        float* vo = (vout_ext ? vout_ext : g_v) + ((size_t)(b0+wid)*N_ + n)*C_;
        vo[lane]      = v0;
        vo[32 + lane] = v1;
    }
    __syncthreads();

    if (compute_p) {
        const int b = t >> 5, dl = t & 31;
        const float* vb = sv + b*C_;
        #pragma unroll
        for (int dd = 0; dd < 8; dd++) {
            int d = dd*32 + dl;
            const float* wr = sW + d*WPAD;
            float acc = 0.f;
            #pragma unroll
            for (int cc = 0; cc < C_; cc++) acc += wr[cc] * vb[cc];
            g_p[((size_t)(b0+b)*N_ + n)*D_ + d] = acc;
        }
    }
}

// pT2 word offset within a d-pair row for capsule index n (bank-swizzled)
__device__ __forceinline__ int pt2_off(int n) {
    int ng = n >> 2;
    return 8*ng + 4*(ng >> 2) + 4*((n >> 1) & 1) + 2*(n & 1);
}

// ---------------- fused routing pass ----------------------------------------
// grid = B_*CHUNKS (512), 512 threads, 2 CTAs/SM.
__global__ __launch_bounds__(TPB, 2) void pass_kernel(const float* __restrict__ x, int first) {
    extern __shared__ float sm[];
    float* xS  = sm;                   // [SCH][XPAD]
    float* pT2 = sm + OFF_PT2;         // [D_/2][PPAD2] d-pair-interleaved, swizzled
    float* cS2 = sm + OFF_PT2;         // [SCH][CS2PAD] duplicated coefs (aliases pT2)
    float* cS  = sm + OFF_CS;          // [SCH][CPAD]

    const int t  = threadIdx.x;
    const int b  = blockIdx.x >> 4;    // CHUNKS = 16
    const int ch = blockIdx.x & 15;
    const int s0 = ch * SCH;

    // load x chunk: SCH rows x 64 float4, coalesced
    {
        const float4* xg = (const float4*)(x + ((size_t)b * S_ + s0) * D_);
        for (int i = t; i < SCH*(D_/4); i += TPB) {
            int s = i >> 6, dq = i & 63;
            *(float4*)&xS[s*XPAD + dq*4] = xg[i];
        }
    }
    // load p[b] -> pT2: element (k=d>>1, n, par=d&1) at k*PPAD2 + pt2_off(n) + par
    {
        const float4* pg = (const float4*)(g_p + (size_t)b * N_ * D_);
        for (int i = t; i < N_*(D_/4); i += TPB) {
            int n = i >> 6, q = i & 63;        // d0 = 4q
            float4 v = pg[i];
            int w0 = (2*q) * PPAD2 + pt2_off(n);
            pT2[w0]         = v.x;             // (2q,   n, 0)
            pT2[w0 + 1]     = v.y;             // (2q,   n, 1)
            pT2[w0 + PPAD2]     = v.z;         // (2q+1, n, 0)
            pT2[w0 + PPAD2 + 1] = v.w;         // (2q+1, n, 1)
        }
    }
    __syncthreads();

    // phase 2: agree[s][n] = sum_d x[s][d] p[n][d]; thread = 1s x 4n, packed over d
    {
        const int ng = t & 7;           // n0 = 4*ng
        const int s  = t >> 3;          // 0..63
        const int pbase = 8*ng + 4*(ng >> 2);
        unsigned long long acc0 = 0, acc1 = 0, acc2 = 0, acc3 = 0;
        #pragma unroll 4
        for (int q = 0; q < 64; q++) {
            ulonglong2 xv = *(const ulonglong2*)&xS[s*XPAD + 4*q];   // d-pairs 2q, 2q+1
            const float* pr = &pT2[(2*q)*PPAD2 + pbase];
            ulonglong2 pa01 = *(const ulonglong2*)(pr);              // k=2q,   n0..n0+1
            ulonglong2 pa23 = *(const ulonglong2*)(pr + 4);          // k=2q,   n0+2..n0+3
            ulonglong2 pb01 = *(const ulonglong2*)(pr + PPAD2);      // k=2q+1, n0..n0+1
            ulonglong2 pb23 = *(const ulonglong2*)(pr + PPAD2 + 4);  // k=2q+1, n0+2..n0+3
            fma2(acc0, xv.x, pa01.x); fma2(acc1, xv.x, pa01.y);
            fma2(acc2, xv.x, pa23.x); fma2(acc3, xv.x, pa23.y);
            fma2(acc0, xv.y, pb01.x); fma2(acc1, xv.y, pb01.y);
            fma2(acc2, xv.y, pb23.x); fma2(acc3, xv.y, pb23.y);
        }
        float2 f0 = unpack2(acc0), f1 = unpack2(acc1);
        float2 f2 = unpack2(acc2), f3 = unpack2(acc3);
        *(float4*)&cS[s*CPAD + 4*ng] =
            make_float4(f0.x + f0.y, f1.x + f1.y, f2.x + f2.y, f3.x + f3.y);
    }
    __syncthreads();

    // softmax over n per s-row; write coefs DUPLICATED into cS2 (overwrites pT2)
    {
        const int wid = t >> 5, lane = t & 31;
        #pragma unroll
        for (int r = 0; r < SCH/16; r++) {
            int s = wid * (SCH/16) + r;
            float lg = cS[s*CPAD + lane];
            size_t li = ((size_t)b * S_ + s0 + s) * N_ + lane;
            if (first) g_logits[li] = lg;
            else       lg += g_logits[li];
            float mx = lg;
            #pragma unroll
            for (int o = 16; o > 0; o >>= 1) mx = fmaxf(mx, __shfl_xor_sync(0xffffffffu, mx, o));
            float e = expf(lg - mx);
            float sum = e;
            #pragma unroll
            for (int o = 16; o > 0; o >>= 1) sum += __shfl_xor_sync(0xffffffffu, sum, o);
            float cv = e / sum;
            *(float2*)&cS2[s*CS2PAD + 2*lane] = make_float2(cv, cv);
        }
    }
    __syncthreads();

    // phase 3: y[n][d] += sum_s c[s][n] x[s][d]; thread = 4n x 4d, packed over d
    {
        const int dg = t & 63;          // d0 = 4*dg
        const int n0 = 4 * (t >> 6);    // 0..28
        unsigned long long acc[4][2];
        #pragma unroll
        for (int i = 0; i < 4; i++) { acc[i][0] = 0; acc[i][1] = 0; }
        #pragma unroll 2
        for (int s = 0; s < SCH; s++) {
            ulonglong2 xv  = *(const ulonglong2*)&xS[s*XPAD + 4*dg];
            ulonglong2 c01 = *(const ulonglong2*)&cS2[s*CS2PAD + 2*n0];      // (c_n0,c_n0),(c_n1,c_n1)
            ulonglong2 c23 = *(const ulonglong2*)&cS2[s*CS2PAD + 2*n0 + 4];  // (c_n2,c_n2),(c_n3,c_n3)
            fma2(acc[0][0], c01.x, xv.x); fma2(acc[0][1], c01.x, xv.y);
            fma2(acc[1][0], c01.y, xv.x); fma2(acc[1][1], c01.y, xv.y);
            fma2(acc[2][0], c23.x, xv.x); fma2(acc[2][1], c23.x, xv.y);
            fma2(acc[3][0], c23.y, xv.x); fma2(acc[3][1], c23.y, xv.y);
        }
        float* yo = (first ? g_ya : g_yb) + (size_t)b * N_ * D_;
        #pragma unroll
        for (int i = 0; i < 4; i++) {
            float2 a = unpack2(acc[i][0]), c = unpack2(acc[i][1]);
            float* row = yo + (n0 + i)*D_ + 4*dg;
            atomicAdd(row + 0, a.x);
            atomicAdd(row + 1, a.y);
            atomicAdd(row + 2, c.x);
            atomicAdd(row + 3, c.y);
        }
    }
}

// ---------------- launch ----------------------------------------------------
extern "C" void kernel_launch(void* const* d_in, const int* in_sizes, int n_in,
                              void* d_out, int out_size) {
    (void)in_sizes; (void)n_in; (void)out_size;
    const float* x = (const float*)d_in[0];
    const float* W = (const float*)d_in[1];
    float* out = (float*)d_out;

    cudaFuncSetAttribute(capsule_kernel, cudaFuncAttributeMaxDynamicSharedMemorySize, CAPS_SMEM);
    cudaFuncSetAttribute(pass_kernel,    cudaFuncAttributeMaxDynamicSharedMemorySize, PASS_SMEM);

    zero_kernel<<<(B_*N_*D_ + 255) / 256, 256>>>();
    reduce_x_kernel<<<B_*8, 256>>>(x);                                  // y0

    capsule_kernel<<<dim3(N_, B_/8), 256, CAPS_SMEM>>>(W, 0, nullptr, 1); // v0, p0
    pass_kernel<<<B_*CHUNKS, TPB, PASS_SMEM>>>(x, 1);                     // iter1 -> g_ya, logits
    capsule_kernel<<<dim3(N_, B_/8), 256, CAPS_SMEM>>>(W, 1, nullptr, 1); // v1, p1
    pass_kernel<<<B_*CHUNKS, TPB, PASS_SMEM>>>(x, 0);                     // iter2 -> g_yb
    capsule_kernel<<<dim3(N_, B_/8), 256, CAPS_SMEM>>>(W, 2, out, 0);     // v2 -> d_out
}

// round 7
// speedup vs baseline: 1.1683x; 1.1683x over previous
#include <cuda_runtime.h>
#include <math.h>
#include <stdint.h>

// Problem constants
#define B_  32
#define S_  1024
#define D_  256
#define N_  32
#define C_  64

// pass kernel tiling
#define SCH 32                // s-values per block
#define CHUNKS (S_/SCH)       // 32
#define TPB 512               // threads per pass block
#define XPAD 260              // xS row stride (floats)
#define PPAD 272              // pS row stride (272 % 32 == 16 -> conflict-free phase2)
#define CPAD 36               // agree/coef row stride
#define WPAD 65               // W smem row stride (capsule)

#define PASS_SMEM  ((SCH*XPAD + N_*PPAD + SCH*CPAD) * 4)          // 72704 B -> 3 CTAs/SM
#define CAPS_SMEM  ((D_*WPAD + 8*D_ + 8*C_ + 8*C_) * 4)           // 78848 B

// ---------------- scratch (device globals; no runtime allocation) ----------
__device__ float g_y0[B_*D_];          // (1/N) * sum_s x
__device__ float g_ya[B_*N_*D_];       // y for iter1
__device__ float g_yb[B_*N_*D_];       // y for iter2
__device__ float g_v [B_*N_*C_];
__device__ float g_p [B_*N_*D_];       // p[b,n,d] = sum_c W[n,d,c] v[b,n,c]
__device__ float g_logits[B_*S_*N_];

// ---------------- zero ------------------------------------------------------
__global__ void zero_kernel() {
    int i = blockIdx.x * blockDim.x + threadIdx.x;
    if (i < B_*D_) g_y0[i] = 0.f;
    if (i < B_*N_*D_) { g_ya[i] = 0.f; g_yb[i] = 0.f; }
}

// ---------------- y0 = (1/N) * sum_s x --------------------------------------
__global__ __launch_bounds__(256) void reduce_x_kernel(const float* __restrict__ x) {
    const int b  = blockIdx.x >> 3;     // 32
    const int sg = blockIdx.x & 7;      // 8 groups x 128 s
    const int d  = threadIdx.x;
    const float* xp = x + ((size_t)b * S_ + sg * 128) * D_ + d;
    float a0 = 0.f, a1 = 0.f, a2 = 0.f, a3 = 0.f;
    #pragma unroll 8
    for (int s = 0; s < 128; s += 4) {
        a0 += xp[(s+0)*D_]; a1 += xp[(s+1)*D_];
        a2 += xp[(s+2)*D_]; a3 += xp[(s+3)*D_];
    }
    atomicAdd(&g_y0[b*D_ + d], (a0+a1+a2+a3) * (1.0f / (float)N_));
}

// ---------------- capsule: s = y@W, v = squash(s), p = W@v -------------------
// grid (N_, B_/8), 256 threads. ysel: 0->g_y0 (n-uniform), 1->g_ya, 2->g_yb.
__global__ __launch_bounds__(256) void capsule_kernel(const float* __restrict__ W,
                                                      int ysel, float* __restrict__ vout_ext,
                                                      int compute_p) {
    extern __shared__ float sm[];
    float* sW = sm;                 // [D_][WPAD]
    float* sy = sW + D_*WPAD;       // [8][D_]
    float* ss = sy + 8*D_;          // [8][C_]
    float* sv = ss + 8*C_;          // [8][C_]

    const int n  = blockIdx.x;
    const int b0 = blockIdx.y * 8;
    const int t  = threadIdx.x;

    const float* Wn = W + (size_t)n * D_ * C_;
    for (int i = t; i < D_*C_; i += 256) {
        int d = i >> 6, c = i & 63;
        sW[d*WPAD + c] = Wn[i];
    }
    const float* ysrc = (ysel == 0) ? g_y0 : (ysel == 1) ? g_ya : g_yb;
    for (int i = t; i < 8*D_; i += 256) {
        int bb = i >> 8, d = i & 255;
        sy[bb*D_ + d] = (ysel == 0) ? ysrc[(b0+bb)*D_ + d]
                                    : ysrc[((size_t)(b0+bb)*N_ + n)*D_ + d];
    }
    __syncthreads();

    // s[b][c] = sum_d y[b][d] * W[d][c]
    {
        const int c = t & 63, bt = t >> 6;
        float s0 = 0.f, s1 = 0.f;
        const float* y0r = sy + (bt*2+0)*D_;
        const float* y1r = sy + (bt*2+1)*D_;
        #pragma unroll 4
        for (int d = 0; d < D_; d++) {
            float w = sW[d*WPAD + c];
            s0 += y0r[d] * w;
            s1 += y1r[d] * w;
        }
        ss[(bt*2+0)*C_ + c] = s0;
        ss[(bt*2+1)*C_ + c] = s1;
    }
    __syncthreads();

    // squash: warp wid handles b = b0+wid
    const int wid = t >> 5, lane = t & 31;
    {
        float a0 = ss[wid*C_ + lane];
        float a1 = ss[wid*C_ + 32 + lane];
        float sq = a0*a0 + a1*a1;
        #pragma unroll
        for (int o = 16; o > 0; o >>= 1) sq += __shfl_xor_sync(0xffffffffu, sq, o);
        float sc = (sq / (1.f + sq)) * rsqrtf(sq + 1e-8f);
        float v0 = a0 * sc, v1 = a1 * sc;
        sv[wid*C_ + lane]      = v0;
        sv[wid*C_ + 32 + lane] = v1;
        float* vo = (vout_ext ? vout_ext : g_v) + ((size_t)(b0+wid)*N_ + n)*C_;
        vo[lane]      = v0;
        vo[32 + lane] = v1;
    }
    __syncthreads();

    // p[b][d] = sum_c W[d][c] * v[b][c]
    if (compute_p) {
        const int b = t >> 5, dl = t & 31;
        const float* vb = sv + b*C_;
        #pragma unroll
        for (int dd = 0; dd < 8; dd++) {
            int d = dd*32 + dl;
            const float* wr = sW + d*WPAD;
            float acc = 0.f;
            #pragma unroll
            for (int cc = 0; cc < C_; cc++) acc += wr[cc] * vb[cc];
            g_p[((size_t)(b0+b)*N_ + n)*D_ + d] = acc;
        }
    }
}

// ---------------- fused routing pass ----------------------------------------
// grid = B_*CHUNKS (1024), 512 threads, 3 CTAs/SM.
// agree = x@p^T; logits update; softmax over n; y += c^T x (atomics).
__global__ __launch_bounds__(TPB, 3) void pass_kernel(const float* __restrict__ x, int first) {
    extern __shared__ float sm[];
    float* xS = sm;                    // [SCH][XPAD]
    float* pS = xS + SCH*XPAD;         // [N_][PPAD]
    float* cS = pS + N_*PPAD;          // [SCH][CPAD]  (agree, then coefficients)

    const int t  = threadIdx.x;
    const int b  = blockIdx.x >> 5;    // CHUNKS = 32
    const int ch = blockIdx.x & 31;
    const int s0 = ch * SCH;

    // load x chunk: SCH rows x 64 float4, coalesced
    {
        const float4* xg = (const float4*)(x + ((size_t)b * S_ + s0) * D_);
        #pragma unroll
        for (int i = t; i < SCH*(D_/4); i += TPB) {
            int s = i >> 6, dq = i & 63;
            *(float4*)&xS[s*XPAD + dq*4] = xg[i];
        }
    }
    // load p[b]: N_ rows x 64 float4
    {
        const float4* pg = (const float4*)(g_p + (size_t)b * N_ * D_);
        #pragma unroll
        for (int i = t; i < N_*(D_/4); i += TPB) {
            int n = i >> 6, dq = i & 63;
            *(float4*)&pS[n*PPAD + dq*4] = pg[i];
        }
    }
    __syncthreads();

    // phase 2: agree[s][n] = sum_d x[s][d] p[n][d]
    // warp sg = t>>5 owns rows {2sg, 2sg+1}; ng = (t>>2)&7 owns n-cols {ng+8j};
    // dqq = t&3 splits the 64 float4-dq's 4 ways (interleaved); quad shfl-reduce.
    {
        const int sg  = t >> 5;
        const int ng  = (t >> 2) & 7;
        const int dqq = t & 3;
        float ag[2][4];
        #pragma unroll
        for (int i = 0; i < 2; i++)
            #pragma unroll
            for (int j = 0; j < 4; j++) ag[i][j] = 0.f;
        #pragma unroll 4
        for (int k = 0; k < 16; k++) {
            const int dq = dqq + 4*k;
            float4 x0 = *(const float4*)&xS[(2*sg+0)*XPAD + dq*4];
            float4 x1 = *(const float4*)&xS[(2*sg+1)*XPAD + dq*4];
            #pragma unroll
            for (int j = 0; j < 4; j++) {
                float4 pv = *(const float4*)&pS[(ng + 8*j)*PPAD + dq*4];
                ag[0][j] += x0.x*pv.x + x0.y*pv.y + x0.z*pv.z + x0.w*pv.w;
                ag[1][j] += x1.x*pv.x + x1.y*pv.y + x1.z*pv.z + x1.w*pv.w;
            }
        }
        #pragma unroll
        for (int i = 0; i < 2; i++)
            #pragma unroll
            for (int j = 0; j < 4; j++) {
                ag[i][j] += __shfl_xor_sync(0xffffffffu, ag[i][j], 1);
                ag[i][j] += __shfl_xor_sync(0xffffffffu, ag[i][j], 2);
            }
        if (dqq == 0) {
            #pragma unroll
            for (int i = 0; i < 2; i++)
                #pragma unroll
                for (int j = 0; j < 4; j++)
                    cS[(2*sg+i)*CPAD + ng + 8*j] = ag[i][j];
        }
    }
    __syncthreads();

    // softmax over n per s-row; 16 warps x 2 rows
    {
        const int wid = t >> 5, lane = t & 31;
        #pragma unroll
        for (int r = 0; r < SCH/16; r++) {
            int s = wid * (SCH/16) + r;
            float lg = cS[s*CPAD + lane];
            size_t li = ((size_t)b * S_ + s0 + s) * N_ + lane;
            if (first) g_logits[li] = lg;
            else       lg += g_logits[li];
            float mx = lg;
            #pragma unroll
            for (int o = 16; o > 0; o >>= 1) mx = fmaxf(mx, __shfl_xor_sync(0xffffffffu, mx, o));
            float e = expf(lg - mx);
            float sum = e;
            #pragma unroll
            for (int o = 16; o > 0; o >>= 1) sum += __shfl_xor_sync(0xffffffffu, sum, o);
            cS[s*CPAD + lane] = e / sum;
        }
    }
    __syncthreads();

    // phase 3: y[n][d] += sum_s c[s][n] * x[s][d]; thread tile 4n x 4d.
    // d = 4*(t&63): lanes consecutive -> conflict-free; c float4 warp-broadcast.
    {
        const int n0 = 4 * (t >> 6);    // 0,4,...,28
        const int dg = t & 63;          // d0 = 4*dg
        float acc[4][4];
        #pragma unroll
        for (int i = 0; i < 4; i++)
            #pragma unroll
            for (int j = 0; j < 4; j++) acc[i][j] = 0.f;
        #pragma unroll 4
        for (int s = 0; s < SCH; s++) {
            float4 xv = *(const float4*)&xS[s*XPAD + 4*dg];
            float4 cv = *(const float4*)&cS[s*CPAD + n0];
            float cr[4] = {cv.x, cv.y, cv.z, cv.w};
            float xr[4] = {xv.x, xv.y, xv.z, xv.w};
            #pragma unroll
            for (int i = 0; i < 4; i++)
                #pragma unroll
                for (int j = 0; j < 4; j++) acc[i][j] += cr[i] * xr[j];
        }
        float* yo = (first ? g_ya : g_yb) + (size_t)b * N_ * D_;
        #pragma unroll
        for (int i = 0; i < 4; i++) {
            float* row = yo + (n0 + i)*D_ + 4*dg;
            #pragma unroll
            for (int j = 0; j < 4; j++) atomicAdd(row + j, acc[i][j]);
        }
    }
}

// ---------------- launch ----------------------------------------------------
extern "C" void kernel_launch(void* const* d_in, const int* in_sizes, int n_in,
                              void* d_out, int out_size) {
    (void)in_sizes; (void)n_in; (void)out_size;
    const float* x = (const float*)d_in[0];
    const float* W = (const float*)d_in[1];
    float* out = (float*)d_out;

    cudaFuncSetAttribute(capsule_kernel, cudaFuncAttributeMaxDynamicSharedMemorySize, CAPS_SMEM);
    cudaFuncSetAttribute(pass_kernel,    cudaFuncAttributeMaxDynamicSharedMemorySize, PASS_SMEM);

    zero_kernel<<<(B_*N_*D_ + 255) / 256, 256>>>();
    reduce_x_kernel<<<B_*8, 256>>>(x);                                  // y0

    capsule_kernel<<<dim3(N_, B_/8), 256, CAPS_SMEM>>>(W, 0, nullptr, 1); // v0, p0
    pass_kernel<<<B_*CHUNKS, TPB, PASS_SMEM>>>(x, 1);                     // iter1 -> g_ya, logits
    capsule_kernel<<<dim3(N_, B_/8), 256, CAPS_SMEM>>>(W, 1, nullptr, 1); // v1, p1
    pass_kernel<<<B_*CHUNKS, TPB, PASS_SMEM>>>(x, 0);                     // iter2 -> g_yb
    capsule_kernel<<<dim3(N_, B_/8), 256, CAPS_SMEM>>>(W, 2, out, 0);     // v2 -> d_out
}